// round 16
// baseline (speedup 1.0000x reference)
#include <cuda_runtime.h>
#include <mma.h>

using namespace nvcuda;

// Problem constants
#define IN_DIM 512
#define BATCH  1024
#define NN1    25
#define NN2    10
#define D1     128
#define D2     128
#define NCLS   41
#define ROWS1  (BATCH * NN1)        // 25600

// Scratch (device globals; no cudaMalloc allowed)
__device__ float g_agg2[ROWS1 * IN_DIM];        // 52.4 MB
__device__ float g_agg1[BATCH * 2 * D2];        // 1 MB (atomic-accumulated)
__device__ float g_h1  [BATCH * 2 * D1];        // 1 MB (atomic-accumulated)

__device__ __forceinline__ void cp16(void* smem_dst, const void* gmem_src) {
    unsigned s = (unsigned)__cvta_generic_to_shared(smem_dst);
    asm volatile("cp.async.cg.shared.global [%0], [%1], 16;\n"
                 :: "r"(s), "l"(gmem_src));
}

// ---------------------------------------------------------------------------
// Kernel A: agg2[i,d] = mean_k flat[i*5120 + d*10 + k], flat = gathered f2 rows
// cp.async gather. Blocks g<2048 also zero g_agg1 and g_h1 (both consumed
// atomically downstream; stream order guarantees completion first).
// ---------------------------------------------------------------------------
__global__ void agg2_kernel(const float* __restrict__ features,
                            const int* __restrict__ ids2) {
    __shared__ __align__(16) float sbuf[NN2 * IN_DIM];
    __shared__ int sIds[NN2];
    const int g   = blockIdx.x;
    const int tid = threadIdx.x;

    if (g < 2048 && tid < 32) {  // 2048 * 128 = 262144 floats each
        reinterpret_cast<float4*>(g_agg1 + g * 128)[tid] =
            make_float4(0.f, 0.f, 0.f, 0.f);
        reinterpret_cast<float4*>(g_h1 + g * 128)[tid] =
            make_float4(0.f, 0.f, 0.f, 0.f);
    }

    if (tid < NN2) sIds[tid] = ids2[g * NN2 + tid];
    __syncthreads();

#pragma unroll
    for (int j = 0; j < 10; j++) {
        const int i  = tid + j * 128;          // 1280 float4 total
        const int r  = i >> 7;
        const int c4 = i & 127;
        cp16(&sbuf[i * 4],
             reinterpret_cast<const float4*>(
                 features + (size_t)sIds[r] * IN_DIM) + c4);
    }
    asm volatile("cp.async.commit_group;\n");
    asm volatile("cp.async.wait_group 0;\n");
    __syncthreads();

    float* outRow = g_agg2 + (size_t)g * IN_DIM;
#pragma unroll
    for (int j = 0; j < 4; j++) {
        const int d = tid + j * 128;
        const float* p = sbuf + d * NN2;
        float s = 0.f;
#pragma unroll
        for (int k = 0; k < NN2; k++) s += p[k];
        outRow[d] = s * (1.0f / NN2);
    }
}

// ---------------------------------------------------------------------------
// Kernel B (merged): grid (232, 2).
//   bx <  200: gemm2 block — h2 = A @ W with FUSED agg1 epilogue.
//              half = by (0: features[ids1]/W2s/b2s, 1: g_agg2/W2n/b2n).
//   bx >= 200: head-half0 block (independent of gemm2 output):
//              j = (bx-200) + 32*by in [0,64): hbx = j&15, kz = j>>4.
//              3xTF32 GEMM of features[ids0] @ W1s K-chunk kz -> atomic g_h1.
// ---------------------------------------------------------------------------
#define BM2 128
#define BK  16
#define LDA 20
#define LDB 132
#define LDC 132
#define GSTG 4
#define G_A_STG (BM2 * LDA)                     // 2560 floats
#define G_B_STG (BK * LDB)                      // 2112 floats
#define G_SMEM_FLOATS (GSTG * (G_A_STG + G_B_STG))
#define G_SMEM_BYTES  (G_SMEM_FLOATS * 4)       // 74752 B
#define HBM 64
#define KCH 128

__global__ __launch_bounds__(256, 2)
void gemm2_kernel(const float* __restrict__ features,
                  const int* __restrict__ ids1,
                  const float* __restrict__ W2s,
                  const float* __restrict__ W2n,
                  const float* __restrict__ b2s,
                  const float* __restrict__ b2n,
                  const int* __restrict__ ids0,
                  const float* __restrict__ W1s) {
    extern __shared__ __align__(16) float dsm[];
    __shared__ int   sIds[BM2];
    __shared__ float sbias[D2];

    const int tid = threadIdx.x;
    const int bx  = blockIdx.x;
    const int warp = tid >> 5;

    if (bx >= 200) {
        // ================= head-half0 path =================
        const int j    = (bx - 200) + 32 * blockIdx.y;   // 0..63
        const int row0 = (j & 15) * HBM;
        const int kb   = (j >> 4) * KCH;
        float* pool = dsm;                         // >= HBM*128 floats
        float* hA = pool;                          // [2][HBM*LDA]
        float* hB = pool + 2 * HBM * LDA;          // [2][BK*LDB]

        if (tid < HBM) sIds[tid] = ids0[row0 + tid];
        __syncthreads();

        auto loadTilesH = [&](int kt, int buf) {
            float* a = hA + buf * (HBM * LDA);
            float* b = hB + buf * (BK * LDB);
            {   // A: 64x16 = 256 f4
                const int r  = tid >> 2;
                const int c4 = tid & 3;
                cp16(&a[r * LDA + c4 * 4],
                     features + (size_t)sIds[r] * IN_DIM + kb + kt * BK + c4 * 4);
            }
#pragma unroll
            for (int u = 0; u < 2; u++) {   // B: 16x128 = 512 f4
                const int i  = tid + u * 256;
                const int r  = i >> 5;
                const int c4 = i & 31;
                cp16(&b[r * LDB + c4 * 4],
                     W1s + (size_t)(kb + kt * BK + r) * 128 + c4 * 4);
            }
            asm volatile("cp.async.commit_group;\n");
        };

        wmma::fragment<wmma::accumulator, 16, 16, 8, float> acc[4];
#pragma unroll
        for (int jj = 0; jj < 4; jj++) wmma::fill_fragment(acc[jj], 0.0f);

        const int m0 = (warp >> 1) * 16;
        const int n0 = (warp & 1) * 64;

        const int nt = KCH / BK;   // 8
        loadTilesH(0, 0);
        for (int kt = 0; kt < nt; kt++) {
            if (kt + 1 < nt) {
                loadTilesH(kt + 1, (kt + 1) & 1);
                asm volatile("cp.async.wait_group 1;\n");
            } else {
                asm volatile("cp.async.wait_group 0;\n");
            }
            __syncthreads();

            const int cur = kt & 1;
            const float* a = hA + cur * (HBM * LDA);
            const float* b = hB + cur * (BK * LDB);
#pragma unroll
            for (int kk = 0; kk < BK; kk += 8) {
                wmma::fragment<wmma::matrix_a, 16, 16, 8, wmma::precision::tf32,
                               wmma::row_major> af, afl;
                wmma::load_matrix_sync(af, &a[m0 * LDA + kk], LDA);
#pragma unroll
                for (int t = 0; t < af.num_elements; t++) {
                    const float hi = wmma::__float_to_tf32(af.x[t]);
                    afl.x[t] = af.x[t] - hi;
                    af.x[t]  = hi;
                }
#pragma unroll
                for (int jj = 0; jj < 4; jj++) {
                    wmma::fragment<wmma::matrix_b, 16, 16, 8, wmma::precision::tf32,
                                   wmma::row_major> bf, bfl;
                    wmma::load_matrix_sync(bf, &b[kk * LDB + n0 + jj * 16], LDB);
#pragma unroll
                    for (int t = 0; t < bf.num_elements; t++) {
                        const float hi = wmma::__float_to_tf32(bf.x[t]);
                        bfl.x[t] = bf.x[t] - hi;
                        bf.x[t]  = hi;
                    }
                    wmma::mma_sync(acc[jj], af,  bfl, acc[jj]);
                    wmma::mma_sync(acc[jj], afl, bf,  acc[jj]);
                    wmma::mma_sync(acc[jj], af,  bf,  acc[jj]);
                }
            }
            __syncthreads();
        }

#pragma unroll
        for (int jj = 0; jj < 4; jj++)
            wmma::store_matrix_sync(pool + (size_t)m0 * 128 + n0 + jj * 16,
                                    acc[jj], 128, wmma::mem_row_major);
        __syncthreads();

#pragma unroll
        for (int u = 0; u < HBM * 128 / 256; u++) {
            const int i = tid + u * 256;
            const int r = i >> 7;
            const int c = i & 127;
            atomicAdd(&g_h1[(size_t)(row0 + r) * (2 * D1) + c], pool[i]);
        }
        return;
    }

    // ================= gemm2 path =================
    float* sA = dsm;
    float* sB = dsm + GSTG * G_A_STG;
    const int half = blockIdx.y;
    const int row0 = bx * BM2;
    const float* __restrict__ W = half ? W2n : W2s;
    const int nt = IN_DIM / BK;            // 32

    if (half == 0 && tid < BM2) sIds[tid] = ids1[row0 + tid];
    if (tid < D2) sbias[tid] = half ? b2n[tid] : b2s[tid];
    __syncthreads();

    auto loadTiles = [&](int kt, int buf) {
        float* a = sA + buf * G_A_STG;
        float* b = sB + buf * G_B_STG;
#pragma unroll
        for (int u = 0; u < 2; u++) {      // A: 128x16 = 512 f4
            const int i  = tid + u * 256;
            const int r  = i >> 2;
            const int c4 = i & 3;
            const float* src = half
                ? g_agg2  + (size_t)(row0 + r) * IN_DIM + kt * BK + c4 * 4
                : features + (size_t)sIds[r] * IN_DIM + kt * BK + c4 * 4;
            cp16(&a[r * LDA + c4 * 4], src);
        }
#pragma unroll
        for (int u = 0; u < 2; u++) {      // B: 16x128 = 512 f4
            const int i  = tid + u * 256;
            const int r  = i >> 5;
            const int c4 = i & 31;
            cp16(&b[r * LDB + c4 * 4],
                 W + (size_t)(kt * BK + r) * 128 + c4 * 4);
        }
        asm volatile("cp.async.commit_group;\n");
    };

    wmma::fragment<wmma::accumulator, 16, 16, 8, float> acc[2][4];
#pragma unroll
    for (int i = 0; i < 2; i++)
#pragma unroll
        for (int j = 0; j < 4; j++) wmma::fill_fragment(acc[i][j], 0.0f);

    const int m0 = (warp >> 1) * 32;   // 0,32,64,96
    const int n0 = (warp & 1) * 64;    // 0,64

    loadTiles(0, 0);
    loadTiles(1, 1);
    loadTiles(2, 2);

    for (int kt = 0; kt < nt; kt++) {
        if (kt + 3 < nt) {
            loadTiles(kt + 3, (kt + 3) & 3);
            asm volatile("cp.async.wait_group 3;\n");
        } else if (kt + 3 == nt) {
            asm volatile("cp.async.wait_group 2;\n");
        } else if (kt + 2 == nt) {
            asm volatile("cp.async.wait_group 1;\n");
        } else {
            asm volatile("cp.async.wait_group 0;\n");
        }
        __syncthreads();

        const int cur = kt & 3;
        const float* a = sA + cur * G_A_STG;
        const float* b = sB + cur * G_B_STG;
#pragma unroll
        for (int kk = 0; kk < BK; kk += 8) {
            wmma::fragment<wmma::matrix_a, 16, 16, 8, wmma::precision::tf32,
                           wmma::row_major> af[2];
            wmma::fragment<wmma::matrix_b, 16, 16, 8, wmma::precision::tf32,
                           wmma::row_major> bf;
#pragma unroll
            for (int i = 0; i < 2; i++)
                wmma::load_matrix_sync(af[i], &a[(m0 + i * 16) * LDA + kk], LDA);
#pragma unroll
            for (int j = 0; j < 4; j++) {
                wmma::load_matrix_sync(bf, &b[kk * LDB + n0 + j * 16], LDB);
                wmma::mma_sync(acc[0][j], af[0], bf, acc[0][j]);
                wmma::mma_sync(acc[1][j], af[1], bf, acc[1][j]);
            }
        }
        __syncthreads();
    }

    // ---- Fused agg1 epilogue (h2 tile stays in smem) ----
#pragma unroll
    for (int i = 0; i < 2; i++)
#pragma unroll
        for (int j = 0; j < 4; j++)
            wmma::store_matrix_sync(
                dsm + (size_t)(m0 + i * 16) * LDC + n0 + j * 16,
                acc[i][j], LDC, wmma::mem_row_major);
    __syncthreads();

    const int q0 = row0 * 256;
    const int g0 = q0 / NN1;
    const int g1 = (q0 + BM2 * 256 - 1) / NN1;
    for (int g = g0 + tid; g <= g1; g += 256) {
        float s = 0.f;
        int   cnt = 0;
        const int qs = g * NN1;
#pragma unroll
        for (int j = 0; j < NN1; j++) {
            const int q = qs + j;
            const int i = (q >> 8) - row0;
            const int d = q & 255;
            if ((unsigned)i < (unsigned)BM2 && (d >> 7) == half) {
                s += fmaxf(dsm[(size_t)i * LDC + (d & 127)] + sbias[d & 127], 0.f);
                cnt++;
            }
        }
        if (cnt) atomicAdd(&g_agg1[g], s * (1.0f / NN1));
    }
}

// ---------------------------------------------------------------------------
// Kernel D1: head GEMM half-1 only (A = g_agg1 @ W1n), split-K 2, 3xTF32,
// atomic into g_h1. grid (16, 2): blockIdx.y = kz (K-chunk of 128).
// ---------------------------------------------------------------------------
__global__ __launch_bounds__(256, 3)
void head_gemm_kernel(const float* __restrict__ W1n) {
    __shared__ __align__(16) float pool[HBM * 128];   // 32.8 KB
    float* sA = pool;                          // [2][HBM*LDA]
    float* sB = pool + 2 * HBM * LDA;          // [2][BK*LDB]

    const int tid  = threadIdx.x;
    const int kz   = blockIdx.y;
    const int row0 = blockIdx.x * HBM;
    const int kb   = kz * KCH;

    auto loadTiles = [&](int kt, int buf) {
        float* a = sA + buf * (HBM * LDA);
        float* b = sB + buf * (BK * LDB);
        {   // A: 64x16 = 256 f4
            const int r  = tid >> 2;
            const int c4 = tid & 3;
            cp16(&a[r * LDA + c4 * 4],
                 g_agg1 + (size_t)(row0 + r) * (2 * D2) + kb + kt * BK + c4 * 4);
        }
#pragma unroll
        for (int u = 0; u < 2; u++) {   // B: 16x128 = 512 f4
            const int i  = tid + u * 256;
            const int r  = i >> 5;
            const int c4 = i & 31;
            cp16(&b[r * LDB + c4 * 4],
                 W1n + (size_t)(kb + kt * BK + r) * 128 + c4 * 4);
        }
        asm volatile("cp.async.commit_group;\n");
    };

    wmma::fragment<wmma::accumulator, 16, 16, 8, float> acc[4];
#pragma unroll
    for (int j = 0; j < 4; j++) wmma::fill_fragment(acc[j], 0.0f);

    const int warp = tid >> 5;
    const int m0 = (warp >> 1) * 16;
    const int n0 = (warp & 1) * 64;

    const int nt = KCH / BK;   // 8
    loadTiles(0, 0);
    for (int kt = 0; kt < nt; kt++) {
        if (kt + 1 < nt) {
            loadTiles(kt + 1, (kt + 1) & 1);
            asm volatile("cp.async.wait_group 1;\n");
        } else {
            asm volatile("cp.async.wait_group 0;\n");
        }
        __syncthreads();

        const int cur = kt & 1;
        const float* a = sA + cur * (HBM * LDA);
        const float* b = sB + cur * (BK * LDB);
#pragma unroll
        for (int kk = 0; kk < BK; kk += 8) {
            wmma::fragment<wmma::matrix_a, 16, 16, 8, wmma::precision::tf32,
                           wmma::row_major> af, afl;
            wmma::load_matrix_sync(af, &a[m0 * LDA + kk], LDA);
#pragma unroll
            for (int t = 0; t < af.num_elements; t++) {
                const float hi = wmma::__float_to_tf32(af.x[t]);
                afl.x[t] = af.x[t] - hi;
                af.x[t]  = hi;
            }
#pragma unroll
            for (int j = 0; j < 4; j++) {
                wmma::fragment<wmma::matrix_b, 16, 16, 8, wmma::precision::tf32,
                               wmma::row_major> bf, bfl;
                wmma::load_matrix_sync(bf, &b[kk * LDB + n0 + j * 16], LDB);
#pragma unroll
                for (int t = 0; t < bf.num_elements; t++) {
                    const float hi = wmma::__float_to_tf32(bf.x[t]);
                    bfl.x[t] = bf.x[t] - hi;
                    bf.x[t]  = hi;
                }
                wmma::mma_sync(acc[j], af,  bfl, acc[j]);
                wmma::mma_sync(acc[j], afl, bf,  acc[j]);
                wmma::mma_sync(acc[j], af,  bf,  acc[j]);
            }
        }
        __syncthreads();
    }

#pragma unroll
    for (int j = 0; j < 4; j++)
        wmma::store_matrix_sync(pool + (size_t)m0 * 128 + n0 + j * 16,
                                acc[j], 128, wmma::mem_row_major);
    __syncthreads();

#pragma unroll
    for (int u = 0; u < HBM * 128 / 256; u++) {
        const int i = tid + u * 256;
        const int r = i >> 7;
        const int c = i & 127;
        atomicAdd(&g_h1[(size_t)(row0 + r) * (2 * D1) + D1 + c], pool[i]);
    }
}

// ---------------------------------------------------------------------------
// Kernel D2: out = (g_h1 + bias) @ Wfc + bfc. 4 rows/block, grid 256.
// Wfc staged in ORIGINAL layout via float4 (cheap); one thread per
// (row, class): sW[k*NCLS+c] is conflict-free across lanes. No shfl.
// ---------------------------------------------------------------------------
#define CRPB 4
__global__ __launch_bounds__(256)
void clf_kernel(const float* __restrict__ b1s,
                const float* __restrict__ b1n,
                const float* __restrict__ Wfc,
                const float* __restrict__ bfc,
                float* __restrict__ out) {
    __shared__ float sW[2 * D1 * NCLS];     // 42 KB
    __shared__ float sH[CRPB * 2 * D1];     // 4 KB
    const int row0 = blockIdx.x * CRPB;
    const int tid  = threadIdx.x;           // 256

    for (int i = tid; i < 2 * D1 * NCLS / 4; i += 256)
        reinterpret_cast<float4*>(sW)[i] =
            reinterpret_cast<const float4*>(Wfc)[i];
    for (int i = tid; i < CRPB * 2 * D1; i += 256) {
        const int c = i & 255;
        const float b = (c < D1) ? b1s[c] : b1n[c - D1];
        sH[i] = g_h1[(size_t)row0 * 2 * D1 + i] + b;
    }
    __syncthreads();

    if (tid < CRPB * NCLS) {               // 164 outputs
        const int r = tid / NCLS;
        const int c = tid % NCLS;
        const float* h = sH + r * 2 * D1;
        float a0 = 0.f, a1 = 0.f, a2 = 0.f, a3 = 0.f;
#pragma unroll 8
        for (int k = 0; k < 2 * D1; k += 4) {
            a0 = fmaf(h[k + 0], sW[(k + 0) * NCLS + c], a0);
            a1 = fmaf(h[k + 1], sW[(k + 1) * NCLS + c], a1);
            a2 = fmaf(h[k + 2], sW[(k + 2) * NCLS + c], a2);
            a3 = fmaf(h[k + 3], sW[(k + 3) * NCLS + c], a3);
        }
        out[(row0 + r) * NCLS + c] = (a0 + a1) + (a2 + a3) + bfc[c];
    }
}

// ---------------------------------------------------------------------------
extern "C" void kernel_launch(void* const* d_in, const int* in_sizes, int n_in,
                              void* d_out, int out_size) {
    const float* features = (const float*)d_in[0];
    const int*   ids0     = (const int*)  d_in[1];
    const int*   ids1     = (const int*)  d_in[2];
    const int*   ids2     = (const int*)  d_in[3];
    const float* W2s      = (const float*)d_in[4];
    const float* b2s      = (const float*)d_in[5];
    const float* W2n      = (const float*)d_in[6];
    const float* b2n      = (const float*)d_in[7];
    const float* W1s      = (const float*)d_in[8];
    const float* b1s      = (const float*)d_in[9];
    const float* W1n      = (const float*)d_in[10];
    const float* b1n      = (const float*)d_in[11];
    const float* Wfc      = (const float*)d_in[12];
    const float* bfc      = (const float*)d_in[13];
    float* out = (float*)d_out;

    cudaFuncSetAttribute(gemm2_kernel,
                         cudaFuncAttributeMaxDynamicSharedMemorySize,
                         G_SMEM_BYTES);

    agg2_kernel<<<ROWS1, 128>>>(features, ids2);
    gemm2_kernel<<<dim3(232, 2), 256, G_SMEM_BYTES>>>(
        features, ids1, W2s, W2n, b2s, b2n, ids0, W1s);
    head_gemm_kernel<<<dim3(BATCH / HBM, 2), 256>>>(W1n);
    clf_kernel<<<BATCH / CRPB, 256>>>(b1s, b1n, Wfc, bfc, out);
}

// round 17
// speedup vs baseline: 1.3939x; 1.3939x over previous
#include <cuda_runtime.h>
#include <mma.h>

using namespace nvcuda;

// Problem constants
#define IN_DIM 512
#define BATCH  1024
#define NN1    25
#define NN2    10
#define D1     128
#define D2     128
#define NCLS   41
#define ROWS1  (BATCH * NN1)        // 25600

// Scratch (device globals; no cudaMalloc allowed)
__device__ float g_agg2[ROWS1 * IN_DIM];        // 52.4 MB
__device__ float g_agg1[BATCH * 2 * D2];        // 1 MB (atomic-accumulated)
__device__ float g_h1  [BATCH * 2 * D1];        // 1 MB (atomic-accumulated)

__device__ __forceinline__ void cp16(void* smem_dst, const void* gmem_src) {
    unsigned s = (unsigned)__cvta_generic_to_shared(smem_dst);
    asm volatile("cp.async.cg.shared.global [%0], [%1], 16;\n"
                 :: "r"(s), "l"(gmem_src));
}

// ---------------------------------------------------------------------------
// Kernel A: agg2[i,d] = mean_k flat[i*5120 + d*10 + k], flat = gathered f2 rows
// cp.async gather. Blocks g<2048 also zero g_agg1 and g_h1 (both consumed
// atomically downstream; stream order guarantees completion first).
// ---------------------------------------------------------------------------
__global__ void agg2_kernel(const float* __restrict__ features,
                            const int* __restrict__ ids2) {
    __shared__ __align__(16) float sbuf[NN2 * IN_DIM];
    __shared__ int sIds[NN2];
    const int g   = blockIdx.x;
    const int tid = threadIdx.x;

    if (g < 2048 && tid < 32) {  // 2048 * 128 = 262144 floats each
        reinterpret_cast<float4*>(g_agg1 + g * 128)[tid] =
            make_float4(0.f, 0.f, 0.f, 0.f);
        reinterpret_cast<float4*>(g_h1 + g * 128)[tid] =
            make_float4(0.f, 0.f, 0.f, 0.f);
    }

    if (tid < NN2) sIds[tid] = ids2[g * NN2 + tid];
    __syncthreads();

#pragma unroll
    for (int j = 0; j < 10; j++) {
        const int i  = tid + j * 128;          // 1280 float4 total
        const int r  = i >> 7;
        const int c4 = i & 127;
        cp16(&sbuf[i * 4],
             reinterpret_cast<const float4*>(
                 features + (size_t)sIds[r] * IN_DIM) + c4);
    }
    asm volatile("cp.async.commit_group;\n");
    asm volatile("cp.async.wait_group 0;\n");
    __syncthreads();

    float* outRow = g_agg2 + (size_t)g * IN_DIM;
#pragma unroll
    for (int j = 0; j < 4; j++) {
        const int d = tid + j * 128;
        const float* p = sbuf + d * NN2;
        float s = 0.f;
#pragma unroll
        for (int k = 0; k < NN2; k++) s += p[k];
        outRow[d] = s * (1.0f / NN2);
    }
}

// ---------------------------------------------------------------------------
// Kernel B: h2 = A @ W with FUSED agg1 epilogue (h2 never hits DRAM).
// BM=128, BN=128, BK=16, 4-stage cp.async in dynamic smem (73 KB).
// blockIdx.y = half (0: features[ids1]/W2s/b2s, 1: g_agg2/W2n/b2n).
// SINGLE barrier per k-tile: wait -> sync -> issue loads(kt+3) -> compute(kt).
// Buffer (kt+3)&3 held tile kt-1, whose compute finished before this sync.
// ---------------------------------------------------------------------------
#define BM2 128
#define BK  16
#define LDA 20
#define LDB 132
#define LDC 132
#define GSTG 4
#define G_A_STG (BM2 * LDA)                     // 2560 floats
#define G_B_STG (BK * LDB)                      // 2112 floats
#define G_SMEM_FLOATS (GSTG * (G_A_STG + G_B_STG))
#define G_SMEM_BYTES  (G_SMEM_FLOATS * 4)       // 74752 B (>= tile 128*132*4)

__global__ __launch_bounds__(256, 2)
void gemm2_kernel(const float* __restrict__ features,
                  const int* __restrict__ ids1,
                  const float* __restrict__ W2s,
                  const float* __restrict__ W2n,
                  const float* __restrict__ b2s,
                  const float* __restrict__ b2n) {
    extern __shared__ __align__(16) float dsm[];
    float* sA = dsm;                       // [GSTG][BM2*LDA]
    float* sB = dsm + GSTG * G_A_STG;      // [GSTG][BK*LDB]
    __shared__ int   sIds[BM2];
    __shared__ float sbias[D2];

    const int tid  = threadIdx.x;
    const int half = blockIdx.y;
    const int row0 = blockIdx.x * BM2;
    const float* __restrict__ W = half ? W2n : W2s;
    const int nt = IN_DIM / BK;            // 32

    if (half == 0 && tid < BM2) sIds[tid] = ids1[row0 + tid];
    if (tid < D2) sbias[tid] = half ? b2n[tid] : b2s[tid];
    __syncthreads();

    auto loadTiles = [&](int kt, int buf) {
        float* a = sA + buf * G_A_STG;
        float* b = sB + buf * G_B_STG;
#pragma unroll
        for (int u = 0; u < 2; u++) {      // A: 128x16 = 512 f4
            const int i  = tid + u * 256;
            const int r  = i >> 2;
            const int c4 = i & 3;
            const float* src = half
                ? g_agg2  + (size_t)(row0 + r) * IN_DIM + kt * BK + c4 * 4
                : features + (size_t)sIds[r] * IN_DIM + kt * BK + c4 * 4;
            cp16(&a[r * LDA + c4 * 4], src);
        }
#pragma unroll
        for (int u = 0; u < 2; u++) {      // B: 16x128 = 512 f4
            const int i  = tid + u * 256;
            const int r  = i >> 5;
            const int c4 = i & 31;
            cp16(&b[r * LDB + c4 * 4],
                 W + (size_t)(kt * BK + r) * 128 + c4 * 4);
        }
        asm volatile("cp.async.commit_group;\n");
    };

    wmma::fragment<wmma::accumulator, 16, 16, 8, float> acc[2][4];
#pragma unroll
    for (int i = 0; i < 2; i++)
#pragma unroll
        for (int j = 0; j < 4; j++) wmma::fill_fragment(acc[i][j], 0.0f);

    const int warp = tid >> 5;
    const int m0 = (warp >> 1) * 32;   // 0,32,64,96
    const int n0 = (warp & 1) * 64;    // 0,64

    loadTiles(0, 0);
    loadTiles(1, 1);
    loadTiles(2, 2);

    for (int kt = 0; kt < nt; kt++) {
        // Retire group kt (own thread), then barrier => all threads' tile kt
        // resident. Committed-after-kt at this point: min(2, nt-1-kt).
        if (kt + 2 < nt)      asm volatile("cp.async.wait_group 2;\n");
        else if (kt + 1 < nt) asm volatile("cp.async.wait_group 1;\n");
        else                  asm volatile("cp.async.wait_group 0;\n");
        __syncthreads();

        if (kt + 3 < nt) loadTiles(kt + 3, (kt + 3) & 3);

        const int cur = kt & 3;
        const float* a = sA + cur * G_A_STG;
        const float* b = sB + cur * G_B_STG;
#pragma unroll
        for (int kk = 0; kk < BK; kk += 8) {
            wmma::fragment<wmma::matrix_a, 16, 16, 8, wmma::precision::tf32,
                           wmma::row_major> af[2];
            wmma::fragment<wmma::matrix_b, 16, 16, 8, wmma::precision::tf32,
                           wmma::row_major> bf;
#pragma unroll
            for (int i = 0; i < 2; i++)
                wmma::load_matrix_sync(af[i], &a[(m0 + i * 16) * LDA + kk], LDA);
#pragma unroll
            for (int j = 0; j < 4; j++) {
                wmma::load_matrix_sync(bf, &b[kk * LDB + n0 + j * 16], LDB);
                wmma::mma_sync(acc[0][j], af[0], bf, acc[0][j]);
                wmma::mma_sync(acc[1][j], af[1], bf, acc[1][j]);
            }
        }
    }
    __syncthreads();   // all compute done before dsm is reused as C tile

    // ---- Fused agg1 epilogue (h2 tile stays in smem) ----
#pragma unroll
    for (int i = 0; i < 2; i++)
#pragma unroll
        for (int j = 0; j < 4; j++)
            wmma::store_matrix_sync(
                dsm + (size_t)(m0 + i * 16) * LDC + n0 + j * 16,
                acc[i][j], LDC, wmma::mem_row_major);
    __syncthreads();

    const int q0 = row0 * 256;
    const int g0 = q0 / NN1;
    const int g1 = (q0 + BM2 * 256 - 1) / NN1;
    for (int g = g0 + tid; g <= g1; g += 256) {
        float s = 0.f;
        int   cnt = 0;
        const int qs = g * NN1;
#pragma unroll
        for (int j = 0; j < NN1; j++) {
            const int q = qs + j;
            const int i = (q >> 8) - row0;
            const int d = q & 255;
            if ((unsigned)i < (unsigned)BM2 && (d >> 7) == half) {
                s += fmaxf(dsm[(size_t)i * LDC + (d & 127)] + sbias[d & 127], 0.f);
                cnt++;
            }
        }
        if (cnt) atomicAdd(&g_agg1[g], s * (1.0f / NN1));
    }
}

// ---------------------------------------------------------------------------
// Kernel D1: split-K head GEMM, 3xTF32, partials ATOMICALLY accumulated
// into g_h1 (zeroed by agg2). grid (16, 2, 4): y = half, z = kz (K=128).
//   half 0: A = features[ids0] (K=512, kz 0..3), W = W1s
//   half 1: A = g_agg1 (K=256, kz 0..1; kz 2..3 exit), W = W1n
// Single barrier per k-tile: wait 0 -> sync -> load(kt+1) -> compute(kt).
// ---------------------------------------------------------------------------
#define HBM 64
#define KCH 128

__global__ __launch_bounds__(256, 3)
void head_gemm_kernel(const float* __restrict__ features,
                      const int* __restrict__ ids0,
                      const float* __restrict__ W1s,
                      const float* __restrict__ W1n) {
    __shared__ __align__(16) float pool[HBM * 128];   // 32.8 KB
    __shared__ int sIds[HBM];
    float* sA = pool;                          // [2][HBM*LDA] = 2560
    float* sB = pool + 2 * HBM * LDA;          // [2][BK*LDB]  = 4224

    const int tid  = threadIdx.x;
    const int half = blockIdx.y;
    const int kz   = blockIdx.z;
    if (half == 1 && kz >= 2) return;
    const int row0 = blockIdx.x * HBM;
    const int kb   = kz * KCH;
    const float* __restrict__ W = half ? W1n : W1s;
    const int strideA = half ? 2 * D2 : IN_DIM;

    if (half == 0 && tid < HBM) sIds[tid] = ids0[row0 + tid];
    __syncthreads();

    auto loadTiles = [&](int kt, int buf) {
        float* a = sA + buf * (HBM * LDA);
        float* b = sB + buf * (BK * LDB);
        {   // A: 64x16 = 256 f4
            const int r  = tid >> 2;
            const int c4 = tid & 3;
            const float* src = half
                ? g_agg1  + (size_t)(row0 + r) * strideA + kb + kt * BK + c4 * 4
                : features + (size_t)sIds[r] * strideA + kb + kt * BK + c4 * 4;
            cp16(&a[r * LDA + c4 * 4], src);
        }
#pragma unroll
        for (int u = 0; u < 2; u++) {   // B: 16x128 = 512 f4
            const int i  = tid + u * 256;
            const int r  = i >> 5;
            const int c4 = i & 31;
            cp16(&b[r * LDB + c4 * 4],
                 W + (size_t)(kb + kt * BK + r) * 128 + c4 * 4);
        }
        asm volatile("cp.async.commit_group;\n");
    };

    wmma::fragment<wmma::accumulator, 16, 16, 8, float> acc[4];
#pragma unroll
    for (int j = 0; j < 4; j++) wmma::fill_fragment(acc[j], 0.0f);

    const int warp = tid >> 5;
    const int m0 = (warp >> 1) * 16;
    const int n0 = (warp & 1) * 64;

    const int nt = KCH / BK;   // 8
    loadTiles(0, 0);
    for (int kt = 0; kt < nt; kt++) {
        asm volatile("cp.async.wait_group 0;\n");
        __syncthreads();
        if (kt + 1 < nt) loadTiles(kt + 1, (kt + 1) & 1);

        const int cur = kt & 1;
        const float* a = sA + cur * (HBM * LDA);
        const float* b = sB + cur * (BK * LDB);
#pragma unroll
        for (int kk = 0; kk < BK; kk += 8) {
            wmma::fragment<wmma::matrix_a, 16, 16, 8, wmma::precision::tf32,
                           wmma::row_major> af, afl;
            wmma::load_matrix_sync(af, &a[m0 * LDA + kk], LDA);
#pragma unroll
            for (int t = 0; t < af.num_elements; t++) {
                const float hi = wmma::__float_to_tf32(af.x[t]);
                afl.x[t] = af.x[t] - hi;
                af.x[t]  = hi;
            }
#pragma unroll
            for (int j = 0; j < 4; j++) {
                wmma::fragment<wmma::matrix_b, 16, 16, 8, wmma::precision::tf32,
                               wmma::row_major> bf, bfl;
                wmma::load_matrix_sync(bf, &b[kk * LDB + n0 + j * 16], LDB);
#pragma unroll
                for (int t = 0; t < bf.num_elements; t++) {
                    const float hi = wmma::__float_to_tf32(bf.x[t]);
                    bfl.x[t] = bf.x[t] - hi;
                    bf.x[t]  = hi;
                }
                wmma::mma_sync(acc[j], af,  bfl, acc[j]);
                wmma::mma_sync(acc[j], afl, bf,  acc[j]);
                wmma::mma_sync(acc[j], af,  bf,  acc[j]);
            }
        }
    }
    __syncthreads();   // all compute done before pool is reused as C tile

    // Dump accumulators to the pool (now free) and atomically fold into g_h1.
#pragma unroll
    for (int j = 0; j < 4; j++)
        wmma::store_matrix_sync(pool + (size_t)m0 * 128 + n0 + j * 16,
                                acc[j], 128, wmma::mem_row_major);
    __syncthreads();

#pragma unroll
    for (int u = 0; u < HBM * 128 / 256; u++) {    // 32 elems/thread
        const int i = tid + u * 256;
        const int r = i >> 7;
        const int c = i & 127;
        atomicAdd(&g_h1[(size_t)(row0 + r) * (2 * D1) + half * D1 + c], pool[i]);
    }
}

// ---------------------------------------------------------------------------
// Kernel D2: out = (g_h1 + bias) @ Wfc + bfc. 4 rows/block, grid 256.
// Wfc staged TRANSPOSED in smem (row stride 257 -> bank = (c+k) mod 32,
// conflict-free). One thread per (row, class); 4 accumulators; no shfl.
// (Measured faster than original-layout staging: 15.5 vs 18.5 us.)
// ---------------------------------------------------------------------------
#define CRPB 4
#define WSTR 257
__global__ __launch_bounds__(256)
void clf_kernel(const float* __restrict__ b1s,
                const float* __restrict__ b1n,
                const float* __restrict__ Wfc,
                const float* __restrict__ bfc,
                float* __restrict__ out) {
    __shared__ float sWt[NCLS * WSTR];      // 42.1 KB (transposed, padded)
    __shared__ float sH[CRPB * 2 * D1];     // 4 KB
    const int row0 = blockIdx.x * CRPB;
    const int tid  = threadIdx.x;           // 256

    // Stage Wfc transposed: coalesced f4 reads, scattered scalar smem writes.
    for (int i4 = tid; i4 < 2 * D1 * NCLS / 4; i4 += 256) {   // 2624
        const float4 v = reinterpret_cast<const float4*>(Wfc)[i4];
        int j = i4 * 4;
        sWt[(j % NCLS) * WSTR + (j / NCLS)] = v.x; j++;
        sWt[(j % NCLS) * WSTR + (j / NCLS)] = v.y; j++;
        sWt[(j % NCLS) * WSTR + (j / NCLS)] = v.z; j++;
        sWt[(j % NCLS) * WSTR + (j / NCLS)] = v.w;
    }
    for (int i = tid; i < CRPB * 2 * D1; i += 256) {
        const int c = i & 255;
        const float b = (c < D1) ? b1s[c] : b1n[c - D1];
        sH[i] = g_h1[(size_t)row0 * 2 * D1 + i] + b;
    }
    __syncthreads();

    if (tid < CRPB * NCLS) {               // 164 outputs
        const int r = tid / NCLS;
        const int c = tid % NCLS;
        const float* h = sH + r * 2 * D1;
        const float* w = sWt + c * WSTR;
        float a0 = 0.f, a1 = 0.f, a2 = 0.f, a3 = 0.f;
#pragma unroll 8
        for (int k = 0; k < 2 * D1; k += 4) {
            a0 = fmaf(h[k + 0], w[k + 0], a0);
            a1 = fmaf(h[k + 1], w[k + 1], a1);
            a2 = fmaf(h[k + 2], w[k + 2], a2);
            a3 = fmaf(h[k + 3], w[k + 3], a3);
        }
        out[(row0 + r) * NCLS + c] = (a0 + a1) + (a2 + a3) + bfc[c];
    }
}

// ---------------------------------------------------------------------------
extern "C" void kernel_launch(void* const* d_in, const int* in_sizes, int n_in,
                              void* d_out, int out_size) {
    const float* features = (const float*)d_in[0];
    const int*   ids0     = (const int*)  d_in[1];
    const int*   ids1     = (const int*)  d_in[2];
    const int*   ids2     = (const int*)  d_in[3];
    const float* W2s      = (const float*)d_in[4];
    const float* b2s      = (const float*)d_in[5];
    const float* W2n      = (const float*)d_in[6];
    const float* b2n      = (const float*)d_in[7];
    const float* W1s      = (const float*)d_in[8];
    const float* b1s      = (const float*)d_in[9];
    const float* W1n      = (const float*)d_in[10];
    const float* b1n      = (const float*)d_in[11];
    const float* Wfc      = (const float*)d_in[12];
    const float* bfc      = (const float*)d_in[13];
    float* out = (float*)d_out;

    cudaFuncSetAttribute(gemm2_kernel,
                         cudaFuncAttributeMaxDynamicSharedMemorySize,
                         G_SMEM_BYTES);

    agg2_kernel<<<ROWS1, 128>>>(features, ids2);
    gemm2_kernel<<<dim3(ROWS1 / BM2, 2), 256, G_SMEM_BYTES>>>(
        features, ids1, W2s, W2n, b2s, b2n);
    head_gemm_kernel<<<dim3(BATCH / HBM, 2, 4), 256>>>(features, ids0, W1s, W1n);
    clf_kernel<<<BATCH / CRPB, 256>>>(b1s, b1n, Wfc, bfc, out);
}